// round 8
// baseline (speedup 1.0000x reference)
#include <cuda_runtime.h>
#include <cuda_bf16.h>
#include <math.h>
#include <stdint.h>

// ---------------------------------------------------------------------------
// GuidedUpsampleUnitGF — conv1/conv2/conv3 via mma.sync bf16 (3-term split)
// NOTE: __device__ globals must NEVER be passed as kernel args from host
//       (host sees shadow symbol -> ATS-readable zeros). Select in device code.
// ---------------------------------------------------------------------------

#define P2    65536
#define C_IN  263
#define CE    256
#define EPS_GF 0.01f

// padded activation planes for conv2: [split 2][py 260][px 264][ch 256] bf16
#define PADH 260
#define PADW 264
#define PADP (PADH * PADW)
#define HPLANE ((size_t)PADP * 256)

#define WT_ELEMS (2 * 25 * 256 * 256)

#define K1PAD 320
#define UPLANE ((size_t)P2 * K1PAD)
#define VPLANE ((size_t)P2 * 256)

#define STAGE_BYTES 65536
#define SMEM_1X1 (3 * STAGE_BYTES)

// conv2 smem: A ring 3 x 32KB, B ring 2 x 33792 (132 rows x 128B x hi/lo)
#define C2_A_STAGE 32768
#define C2_B_OFF   98304
#define C2_B_SLOT  33792
#define C2_B_SPLIT 16896
#define SMEM_C2    (C2_B_OFF + 2 * C2_B_SLOT)   // 165888

// -------------------- scratch ----------------------------------------------
__device__ __align__(256) float g_A [C_IN * P2];        // upsampled concat; later 'a'
__device__ __align__(256) float g_Ct[(size_t)P2 * 256]; // px-major conv2 out
__device__ __align__(256) float g_F [(size_t)P2 * 256]; // 'b' of guided filter
__device__ __align__(256) float g_guide[P2];
__device__ __align__(256) float g_meanI[P2];
__device__ __align__(256) float g_varI[P2];
__device__ __align__(256) __nv_bfloat16 g_H [2 * HPLANE];     // conv1 out hi/lo padded
__device__ __align__(256) __nv_bfloat16 g_Wt[WT_ELEMS];       // conv2 W hi/lo
__device__ __align__(256) __nv_bfloat16 g_U [2 * UPLANE];     // conv1 input px-major hi/lo
__device__ __align__(256) __nv_bfloat16 g_V [2 * VPLANE];     // conv3 input hi/lo (filt)
__device__ __align__(256) __nv_bfloat16 g_W1[2 * 256 * K1PAD];
__device__ __align__(256) __nv_bfloat16 g_W3[2 * 256 * 256];

// -------------------- helpers ----------------------------------------------
__device__ __forceinline__ uint32_t smem_u32(const void* p) {
    uint32_t a;
    asm("{ .reg .u64 t; cvta.to.shared.u64 t, %1; cvt.u32.u64 %0, t; }" : "=r"(a) : "l"(p));
    return a;
}
__device__ __forceinline__ void cpa16(uint32_t dst, const void* src) {
    asm volatile("cp.async.cg.shared.global [%0], [%1], 16;\n" :: "r"(dst), "l"(src));
}
__device__ __forceinline__ void ldsm4(uint32_t* r, uint32_t addr) {
    asm volatile("ldmatrix.sync.aligned.m8n8.x4.shared.b16 {%0,%1,%2,%3}, [%4];"
                 : "=r"(r[0]), "=r"(r[1]), "=r"(r[2]), "=r"(r[3]) : "r"(addr));
}
__device__ __forceinline__ void mma_bf16(float* d, const uint32_t* a,
                                         uint32_t b0, uint32_t b1) {
    asm volatile("mma.sync.aligned.m16n8k16.row.col.f32.bf16.bf16.f32 "
                 "{%0,%1,%2,%3}, {%4,%5,%6,%7}, {%8,%9}, {%0,%1,%2,%3};"
                 : "+f"(d[0]), "+f"(d[1]), "+f"(d[2]), "+f"(d[3])
                 : "r"(a[0]), "r"(a[1]), "r"(a[2]), "r"(a[3]), "r"(b0), "r"(b1));
}

// -------------------- bilinear 2x upsample ---------------------------------
__global__ void k_upsample(const float* __restrict__ fg,
                           const float* __restrict__ bg,
                           const float* __restrict__ mask,
                           const float* __restrict__ feat)
{
    int idx = blockIdx.x * blockDim.x + threadIdx.x;
    if (idx >= C_IN * P2) return;
    int c = idx >> 16;
    int p = idx & 65535;
    int y = p >> 8, x = p & 255;

    const float* src;
    if (c == 0)      src = mask;
    else if (c <= 3) src = fg + (c - 1) * 16384;
    else if (c <= 6) src = bg + (c - 4) * 16384;
    else             src = feat + (c - 7) * 16384;

    float sy = 0.5f * (float)y - 0.25f;
    float sx = 0.5f * (float)x - 0.25f;
    float fy = sy - floorf(sy);
    float fx = sx - floorf(sx);
    int y0 = (int)floorf(sy);
    int x0 = (int)floorf(sx);
    int y0c = max(y0, 0),       x0c = max(x0, 0);
    int y1c = min(y0 + 1, 127), x1c = min(x0 + 1, 127);

    float v00 = src[y0c * 128 + x0c];
    float v01 = src[y0c * 128 + x1c];
    float v10 = src[y1c * 128 + x0c];
    float v11 = src[y1c * 128 + x1c];
    g_A[idx] = (1.f - fy) * ((1.f - fx) * v00 + fx * v01)
             +        fy  * ((1.f - fx) * v10 + fx * v11);
}

__global__ void k_guide()
{
    int p = blockIdx.x * blockDim.x + threadIdx.x;
    if (p >= P2) return;
    g_guide[p] = (g_A[P2 + p] + g_A[2 * P2 + p] + g_A[3 * P2 + p]) * (128.0f / 3.0f);
}

__device__ __forceinline__ int cnt_axis(int i)
{
    return min(i + 2, 255) - max(i - 2, 0) + 1;
}

__global__ void k_istats()
{
    int p = blockIdx.x * blockDim.x + threadIdx.x;
    if (p >= P2) return;
    int y = p >> 8, x = p & 255;
    float sI = 0.f, sI2 = 0.f;
    for (int dy = -2; dy <= 2; dy++) {
        int yy = y + dy;
        if (yy < 0 || yy > 255) continue;
        for (int dx = -2; dx <= 2; dx++) {
            int xx = x + dx;
            if (xx < 0 || xx > 255) continue;
            float v = g_guide[yy * 256 + xx];
            sI += v; sI2 += v * v;
        }
    }
    float inv = 1.f / (float)(cnt_axis(y) * cnt_axis(x));
    float mI = sI * inv;
    g_meanI[p] = mI;
    g_varI[p]  = sI2 * inv - mI * mI;
}

// -------------------- operand prep kernels ---------------------------------
// conv1 input: transpose ch-major g_A -> px-major bf16 hi/lo g_U[p][320]
__global__ void k_prepact1()
{
    __shared__ float tile[32][33];
    int p0 = blockIdx.x * 32;
    int c0 = blockIdx.y * 32;
    int tx = threadIdx.x, ty = threadIdx.y;   // 32 x 8
#pragma unroll
    for (int k = 0; k < 4; k++) {
        int ch = c0 + ty + k * 8;
        tile[ty + k * 8][tx] = (ch < C_IN) ? g_A[(size_t)ch * P2 + p0 + tx] : 0.f;
    }
    __syncthreads();
#pragma unroll
    for (int k = 0; k < 4; k++) {
        int p = p0 + ty + k * 8;
        int ch = c0 + tx;
        float v = tile[tx][ty + k * 8];
        __nv_bfloat16 hi = __float2bfloat16(v);
        g_U[(size_t)p * K1PAD + ch] = hi;
        g_U[UPLANE + (size_t)p * K1PAD + ch] = __float2bfloat16(v - __bfloat162float(hi));
    }
}

// conv2 weights: g_Wt[s][tap][m][ch]
__global__ void k_prepw(const float* __restrict__ w2)
{
    int idx = blockIdx.x * blockDim.x + threadIdx.x;
    if (idx >= WT_ELEMS) return;
    int ch = idx & 255;
    int m  = (idx >> 8) & 255;
    int st = idx >> 16;
    int tap = st % 25;
    int s   = st / 25;
    float w = w2[(size_t)m * 6400 + ch * 25 + tap];
    __nv_bfloat16 hi = __float2bfloat16(w);
    g_Wt[idx] = s ? __float2bfloat16(w - __bfloat162float(hi)) : hi;
}

// conv1 weights: g_W1[s][m][320] (zero-pad ch >= 263)
__global__ void k_prepw1(const float* __restrict__ w1)
{
    int idx = blockIdx.x * blockDim.x + threadIdx.x;
    if (idx >= 2 * 256 * K1PAD) return;
    int ch = idx % K1PAD;
    int m  = (idx / K1PAD) & 255;
    int s  = idx / (K1PAD * 256);
    float w = (ch < C_IN) ? w1[(size_t)m * C_IN + ch] : 0.f;
    __nv_bfloat16 hi = __float2bfloat16(w);
    g_W1[idx] = s ? __float2bfloat16(w - __bfloat162float(hi)) : hi;
}

// conv3 weights: g_W3[s][m][256]
__global__ void k_prepw3(const float* __restrict__ w3)
{
    int idx = blockIdx.x * blockDim.x + threadIdx.x;
    if (idx >= 2 * 256 * 256) return;
    int ch = idx & 255;
    int m  = (idx >> 8) & 255;
    int s  = idx >> 16;
    float w = w3[(size_t)m * 256 + ch];
    __nv_bfloat16 hi = __float2bfloat16(w);
    g_W3[idx] = s ? __float2bfloat16(w - __bfloat162float(hi)) : hi;
}

// -------------------- generic 1x1 conv MMA kernel --------------------------
// MODE 0: A=g_W1, B=g_U, epilogue -> g_H bf16 hi/lo padded px-major (conv1)
// MODE 1: A=g_W3, B=g_V, epilogue -> Out fp32 ch-major (conv3)
template<int NKC, int MODE>
__global__ void __launch_bounds__(256, 1) k_mma1x1(const float* __restrict__ bias,
                                                   float* __restrict__ Out)
{
    constexpr int KPAD = NKC * 64;
    constexpr long APLANE_B = (long)256 * KPAD * 2;
    constexpr long BPLANE_B = (long)P2 * KPAD * 2;

    extern __shared__ __align__(1024) char smem[];
    uint32_t sb = smem_u32(smem);
    const int tid = threadIdx.x;
    const int lane = tid & 31, wid = tid >> 5;
    const int wm = wid >> 1, wn = wid & 1;
    const int n0 = blockIdx.x * 128;
    const int m0 = blockIdx.y * 128;

    const int rb = tid >> 3;
    const int cc = tid & 7;
    // device-side symbol references (NOT kernel args!)
    const char* AB = (MODE == 0) ? (const char*)g_W1 : (const char*)g_W3;
    const char* BB = (MODE == 0) ? (const char*)g_U  : (const char*)g_V;

    uint32_t aRow[2], aSw[2];
    const uint32_t aHi = lane >> 4;
#pragma unroll
    for (int f = 0; f < 2; f++) {
        int r = wm * 32 + f * 16 + (lane & 15);
        aRow[f] = r << 7;
        aSw[f] = r & 7;
    }
    uint32_t bRow[4], bSw[4];
    const uint32_t bHi = (lane >> 3) & 1;
#pragma unroll
    for (int g = 0; g < 4; g++) {
        int r = wn * 64 + g * 16 + (lane & 7) + ((lane >> 4) << 3);
        bRow[g] = r << 7;
        bSw[g] = r & 7;
    }

    float acc[2][8][4];
#pragma unroll
    for (int i = 0; i < 2; i++)
#pragma unroll
        for (int j = 0; j < 8; j++)
#pragma unroll
            for (int e = 0; e < 4; e++) acc[i][j][e] = 0.f;

    auto fill = [&](int it) {
        uint32_t stg = sb + (it % 3) * STAGE_BYTES;
        long kO = (long)it * 128;   // 64 ch * 2B
#pragma unroll
        for (int t = 0; t < 4; t++) {
            int r = rb + 32 * t;
            uint32_t sw = (uint32_t)((cc ^ (r & 7)) << 4);
            long a0 = (long)(m0 + r) * (KPAD * 2) + kO + cc * 16;
            cpa16(stg + r * 128 + sw,         AB + a0);
            cpa16(stg + 16384 + r * 128 + sw, AB + a0 + APLANE_B);
            long b0 = (long)(n0 + r) * (KPAD * 2) + kO + cc * 16;
            cpa16(stg + 32768 + r * 128 + sw, BB + b0);
            cpa16(stg + 49152 + r * 128 + sw, BB + b0 + BPLANE_B);
        }
        asm volatile("cp.async.commit_group;" ::: "memory");
    };

    fill(0);
    fill(1);

    for (int it = 0; it < NKC; it++) {
        if (it == NKC - 1) asm volatile("cp.async.wait_group 0;" ::: "memory");
        else               asm volatile("cp.async.wait_group 1;" ::: "memory");
        __syncthreads();
        uint32_t stg = sb + (it % 3) * STAGE_BYTES;
#pragma unroll
        for (int ks = 0; ks < 4; ks++) {
            uint32_t Wh[2][4], Wl[2][4], Bh[4][4], Bl[4][4];
#pragma unroll
            for (int f = 0; f < 2; f++) {
                uint32_t col = ((((uint32_t)(ks << 1) + aHi) ^ aSw[f]) << 4);
                ldsm4(Wh[f], stg + aRow[f] + col);
                ldsm4(Wl[f], stg + 16384 + aRow[f] + col);
            }
#pragma unroll
            for (int g = 0; g < 4; g++) {
                uint32_t col = ((((uint32_t)(ks << 1) + bHi) ^ bSw[g]) << 4);
                ldsm4(Bh[g], stg + 32768 + bRow[g] + col);
                ldsm4(Bl[g], stg + 49152 + bRow[g] + col);
            }
#pragma unroll
            for (int f = 0; f < 2; f++)
#pragma unroll
                for (int g = 0; g < 4; g++)
#pragma unroll
                    for (int h = 0; h < 2; h++) {
                        float* d = acc[f][g * 2 + h];
                        mma_bf16(d, Wh[f], Bh[g][h * 2], Bh[g][h * 2 + 1]);
                        mma_bf16(d, Wh[f], Bl[g][h * 2], Bl[g][h * 2 + 1]);
                        mma_bf16(d, Wl[f], Bh[g][h * 2], Bh[g][h * 2 + 1]);
                    }
        }
        if (it + 2 < NKC) fill(it + 2);
    }
    __syncthreads();

    // ---- staged epilogue ----
    const int l4 = lane >> 2, l2 = (lane & 3) * 2;
    if (MODE == 0) {
        uint32_t* sU = (uint32_t*)smem;   // [n 128][pitch 130] packed (hi,lo)
#pragma unroll
        for (int f = 0; f < 2; f++) {
            int mb = wm * 32 + f * 16 + l4;
            float b0v = bias[m0 + mb], b1v = bias[m0 + mb + 8];
#pragma unroll
            for (int j = 0; j < 8; j++) {
                int nl = wn * 64 + j * 8 + l2;
#pragma unroll
                for (int e = 0; e < 4; e++) {
                    float v = acc[f][j][e] + ((e & 2) ? b1v : b0v);
                    v = fmaxf(v, 0.f);
                    __nv_bfloat16 hi = __float2bfloat16(v);
                    __nv_bfloat16 lo = __float2bfloat16(v - __bfloat162float(hi));
                    uint32_t u = (uint32_t)__bfloat16_as_ushort(hi)
                               | ((uint32_t)__bfloat16_as_ushort(lo) << 16);
                    sU[(nl + (e & 1)) * 130 + mb + ((e & 2) ? 8 : 0)] = u;
                }
            }
        }
        __syncthreads();
#pragma unroll 8
        for (int t = 0; t < 64; t++) {
            int idx = tid + t * 256;
            int row = idx >> 7, ml = idx & 127;
            uint32_t u = sU[row * 130 + ml];
            int ng = n0 + row;
            size_t pixpad = (size_t)(((ng >> 8) + 2) * PADW + (ng & 255) + 2) * 256 + m0 + ml;
            g_H[pixpad] = __ushort_as_bfloat16((unsigned short)(u & 0xFFFF));
            g_H[HPLANE + pixpad] = __ushort_as_bfloat16((unsigned short)(u >> 16));
        }
    } else {
        float* sF = (float*)smem;   // [m 128][pitch 130]
#pragma unroll
        for (int f = 0; f < 2; f++) {
            int mb = wm * 32 + f * 16 + l4;
            float b0v = bias[m0 + mb], b1v = bias[m0 + mb + 8];
#pragma unroll
            for (int j = 0; j < 8; j++) {
                int nl = wn * 64 + j * 8 + l2;
#pragma unroll
                for (int e = 0; e < 4; e++) {
                    float v = acc[f][j][e] + ((e & 2) ? b1v : b0v);
                    sF[(mb + ((e & 2) ? 8 : 0)) * 130 + nl + (e & 1)] = fmaxf(v, 0.f);
                }
            }
        }
        __syncthreads();
#pragma unroll 8
        for (int t = 0; t < 64; t++) {
            int idx = tid + t * 256;
            int ml = idx >> 7, nl = idx & 127;
            Out[(size_t)(m0 + ml) * P2 + n0 + nl] = sF[ml * 130 + nl];
        }
    }
}

// -------------------- conv2: mma.sync bf16, B reused across dx -------------
// loop order: it = (dy*4 + chunk)*5 + dx ; B tile (132 halo rows) per (dy,chunk)
__global__ void __launch_bounds__(256, 1) k_conv2mma(const float* __restrict__ bias2)
{
    extern __shared__ __align__(1024) char smem[];
    uint32_t sb = smem_u32(smem);
    const int tid = threadIdx.x;
    const int lane = tid & 31, wid = tid >> 5;
    const int wm = wid >> 1, wn = wid & 1;
    const int bx = blockIdx.x;
    const int y = bx >> 1, x0 = (bx & 1) * 128;
    const int m0 = blockIdx.y * 128;
    const int pixbase = y * 256 + x0;

    const int rb = tid >> 3;
    const int cc = tid & 7;
    const char* WtB = (const char*)g_Wt;
    const char* HB  = (const char*)g_H;

    uint32_t aRow[2], aSw[2];
    const uint32_t aHi = lane >> 4;
#pragma unroll
    for (int f = 0; f < 2; f++) {
        int r = wm * 32 + f * 16 + (lane & 15);
        aRow[f] = r << 7;
        aSw[f] = r & 7;
    }
    uint32_t rB0[4];
    const uint32_t bHi = (lane >> 3) & 1;
#pragma unroll
    for (int g = 0; g < 4; g++)
        rB0[g] = wn * 64 + g * 16 + (lane & 7) + ((lane >> 4) << 3);

    float acc[2][8][4];
#pragma unroll
    for (int i = 0; i < 2; i++)
#pragma unroll
        for (int j = 0; j < 8; j++)
#pragma unroll
            for (int e = 0; e < 4; e++) acc[i][j][e] = 0.f;

    auto fill = [&](int it) {
        int dy = it / 20, rem = it % 20, chunk = rem / 5, dx = rem % 5;
        int tap = dy * 5 + dx;
        const char* srcA = WtB + (long)tap * 131072 + chunk * 128;
        uint32_t stgA = sb + (it % 3) * C2_A_STAGE;
#pragma unroll
        for (int t = 0; t < 4; t++) {
            int r = rb + 32 * t;
            uint32_t sw = (uint32_t)((cc ^ (r & 7)) << 4);
            long a0 = (long)(m0 + r) * 512 + cc * 16;
            cpa16(stgA + r * 128 + sw,         srcA + a0);
            cpa16(stgA + 16384 + r * 128 + sw, srcA + a0 + 3276800);
        }
        if (dx == 0) {
            uint32_t stgB = sb + C2_B_OFF + ((it / 5) & 1) * C2_B_SLOT;
            const char* srcB = HB + (long)((y + dy) * PADW + x0) * 512 + chunk * 128;
            for (int o = tid * 16; o < C2_B_SPLIT; o += 4096) {
                int r = o >> 7;
                int cB = o & 127;
                uint32_t sw = (uint32_t)(r * 128 + (cB ^ ((r & 7) << 4)));
                cpa16(stgB + sw,              srcB + (long)r * 512 + cB);
                cpa16(stgB + C2_B_SPLIT + sw, srcB + (long)r * 512 + cB + (long)HPLANE * 2);
            }
        }
        asm volatile("cp.async.commit_group;" ::: "memory");
    };

    fill(0);
    fill(1);

    for (int it = 0; it < 100; it++) {
        if (it == 99) asm volatile("cp.async.wait_group 0;" ::: "memory");
        else          asm volatile("cp.async.wait_group 1;" ::: "memory");
        __syncthreads();
        const int dxi = it % 5;
        uint32_t stgA = sb + (it % 3) * C2_A_STAGE;
        uint32_t stgB = sb + C2_B_OFF + ((it / 5) & 1) * C2_B_SLOT;
#pragma unroll
        for (int ks = 0; ks < 4; ks++) {
            uint32_t Wh[2][4], Wl[2][4], Bh[4][4], Bl[4][4];
#pragma unroll
            for (int f = 0; f < 2; f++) {
                uint32_t col = ((((uint32_t)(ks << 1) + aHi) ^ aSw[f]) << 4);
                ldsm4(Wh[f], stgA + aRow[f] + col);
                ldsm4(Wl[f], stgA + 16384 + aRow[f] + col);
            }
#pragma unroll
            for (int g = 0; g < 4; g++) {
                uint32_t rr = rB0[g] + dxi;
                uint32_t addr = stgB + (rr << 7)
                              + ((((uint32_t)(ks << 1) + bHi) ^ (rr & 7)) << 4);
                ldsm4(Bh[g], addr);
                ldsm4(Bl[g], addr + C2_B_SPLIT);
            }
#pragma unroll
            for (int f = 0; f < 2; f++)
#pragma unroll
                for (int g = 0; g < 4; g++)
#pragma unroll
                    for (int h = 0; h < 2; h++) {
                        float* d = acc[f][g * 2 + h];
                        mma_bf16(d, Wh[f], Bh[g][h * 2], Bh[g][h * 2 + 1]);
                        mma_bf16(d, Wh[f], Bl[g][h * 2], Bl[g][h * 2 + 1]);
                        mma_bf16(d, Wl[f], Bh[g][h * 2], Bh[g][h * 2 + 1]);
                    }
        }
        if (it + 2 < 100) fill(it + 2);
    }
    __syncthreads();

    // staged epilogue -> g_Ct px-major, coalesced
    const int l4 = lane >> 2, l2 = (lane & 3) * 2;
    float* sF = (float*)smem;   // [n 128][pitch 130]
#pragma unroll
    for (int f = 0; f < 2; f++) {
        int mb = wm * 32 + f * 16 + l4;
        float b0v = bias2[m0 + mb], b1v = bias2[m0 + mb + 8];
#pragma unroll
        for (int j = 0; j < 8; j++) {
            int nl = wn * 64 + j * 8 + l2;
#pragma unroll
            for (int e = 0; e < 4; e++) {
                float v = acc[f][j][e] + ((e & 2) ? b1v : b0v);
                sF[(nl + (e & 1)) * 130 + mb + ((e & 2) ? 8 : 0)] = fmaxf(v, 0.f);
            }
        }
    }
    __syncthreads();
#pragma unroll 8
    for (int t = 0; t < 64; t++) {
        int idx = tid + t * 256;
        int row = idx >> 7, ml = idx & 127;
        g_Ct[(size_t)(pixbase + row) * 256 + m0 + ml] = sF[row * 130 + ml];
    }
}

// -------------------- fused guided filter ----------------------------------
// Pass A: p -> a (g_A), b (g_F). Rolling 5-row ring of x-rowsums.
// grid (32 x-tiles of 8, 8 y-segs of 32, 8 c-groups of 32), 256 threads.
__global__ void __launch_bounds__(256) k_gfA()
{
    __shared__ float sp[2][12 * 32];
    __shared__ float sg[2][12];
    const int tid = threadIdx.x;
    const int c = tid & 31, xi = tid >> 5;
    const int x0 = blockIdx.x * 8;
    const int ys = blockIdx.y * 32;
    const int c0 = blockIdx.z * 32;
    const int x = x0 + xi;
    float rp[5], rip[5];

    for (int s = 0; s < 36; s++) {
        int row = ys - 2 + s;
        int buf = s & 1;
        if ((unsigned)row < 256u) {
            {
                int xg = x0 + xi - 2;
                sp[buf][xi * 32 + c] = ((unsigned)xg < 256u)
                    ? g_Ct[((size_t)row * 256 + xg) * 256 + c0 + c] : 0.f;
            }
            if (tid < 128) {
                int j = 8 + (tid >> 5);
                int xg = x0 + j - 2;
                sp[buf][j * 32 + c] = ((unsigned)xg < 256u)
                    ? g_Ct[((size_t)row * 256 + xg) * 256 + c0 + c] : 0.f;
            }
            if (tid < 12) {
                int xg = x0 + tid - 2;
                sg[buf][tid] = ((unsigned)xg < 256u) ? g_guide[row * 256 + xg] : 0.f;
            }
        }
        __syncthreads();
        if ((unsigned)row < 256u) {
            float sv = 0.f, si = 0.f;
#pragma unroll
            for (int d = 0; d < 5; d++) {
                float pv = sp[buf][(xi + d) * 32 + c];
                sv += pv;
                si += pv * sg[buf][xi + d];
            }
            rp[row % 5] = sv;
            rip[row % 5] = si;
        }
        int yo = row - 2;
        if (yo >= ys && yo < ys + 32 && yo < 256) {
            float sv = 0.f, si = 0.f;
            int lo = max(yo - 2, 0), hi = min(yo + 2, 255);
            for (int r = lo; r <= hi; r++) { sv += rp[r % 5]; si += rip[r % 5]; }
            float inv = 1.f / (float)(cnt_axis(yo) * cnt_axis(x));
            float mp = sv * inv, mIp = si * inv;
            float mI = g_meanI[yo * 256 + x];
            float a = (mIp - mI * mp) / (g_varI[yo * 256 + x] + EPS_GF);
            size_t o = ((size_t)yo * 256 + x) * 256 + c0 + c;
            g_A[o] = a;
            g_F[o] = mp - a * mI;
        }
    }
}

// Pass B: mean(a)*I + mean(b) -> g_V hi/lo bf16 (conv3 input)
__global__ void __launch_bounds__(256) k_gfB()
{
    __shared__ float sa[2][12 * 32];
    __shared__ float sbv[2][12 * 32];
    const int tid = threadIdx.x;
    const int c = tid & 31, xi = tid >> 5;
    const int x0 = blockIdx.x * 8;
    const int ys = blockIdx.y * 32;
    const int c0 = blockIdx.z * 32;
    const int x = x0 + xi;
    float ra[5], rb[5];

    for (int s = 0; s < 36; s++) {
        int row = ys - 2 + s;
        int buf = s & 1;
        if ((unsigned)row < 256u) {
            {
                int xg = x0 + xi - 2;
                bool v = (unsigned)xg < 256u;
                size_t o = ((size_t)row * 256 + xg) * 256 + c0 + c;
                sa [buf][xi * 32 + c] = v ? g_A[o] : 0.f;
                sbv[buf][xi * 32 + c] = v ? g_F[o] : 0.f;
            }
            if (tid < 128) {
                int j = 8 + (tid >> 5);
                int xg = x0 + j - 2;
                bool v = (unsigned)xg < 256u;
                size_t o = ((size_t)row * 256 + xg) * 256 + c0 + c;
                sa [buf][j * 32 + c] = v ? g_A[o] : 0.f;
                sbv[buf][j * 32 + c] = v ? g_F[o] : 0.f;
            }
        }
        __syncthreads();
        if ((unsigned)row < 256u) {
            float s1 = 0.f, s2 = 0.f;
#pragma unroll
            for (int d = 0; d < 5; d++) {
                s1 += sa [buf][(xi + d) * 32 + c];
                s2 += sbv[buf][(xi + d) * 32 + c];
            }
            ra[row % 5] = s1;
            rb[row % 5] = s2;
        }
        int yo = row - 2;
        if (yo >= ys && yo < ys + 32 && yo < 256) {
            float s1 = 0.f, s2 = 0.f;
            int lo = max(yo - 2, 0), hi = min(yo + 2, 255);
            for (int r = lo; r <= hi; r++) { s1 += ra[r % 5]; s2 += rb[r % 5]; }
            float inv = 1.f / (float)(cnt_axis(yo) * cnt_axis(x));
            float filt = (s1 * inv) * g_guide[yo * 256 + x] + s2 * inv;
            __nv_bfloat16 fh = __float2bfloat16(filt);
            size_t o = ((size_t)yo * 256 + x) * 256 + c0 + c;
            g_V[o] = fh;
            g_V[VPLANE + o] = __float2bfloat16(filt - __bfloat162float(fh));
        }
    }
}

// -------------------- mask head --------------------------------------------
__global__ void k_maskhead(const float* __restrict__ featOut,
                           const float* __restrict__ wm,
                           const float* __restrict__ bm,
                           float* __restrict__ maskOut)
{
    __shared__ float sw[256];
    int tid = threadIdx.x;
    sw[tid] = wm[tid];
    __syncthreads();
    int p = blockIdx.x * blockDim.x + tid;
    if (p >= P2) return;
    float s = bm[0];
#pragma unroll 8
    for (int c = 0; c < 256; c++)
        s += sw[c] * featOut[(size_t)c * P2 + p];
    maskOut[p] = 1.f / (1.f + expf(-s));
}

// ---------------------------------------------------------------------------
extern "C" void kernel_launch(void* const* d_in, const int* in_sizes, int n_in,
                              void* d_out, int out_size)
{
    const float* fg   = (const float*)d_in[0];
    const float* bg   = (const float*)d_in[1];
    const float* mask = (const float*)d_in[2];
    const float* feat = (const float*)d_in[3];
    const float* w1   = (const float*)d_in[4];
    const float* b1   = (const float*)d_in[5];
    const float* w2   = (const float*)d_in[6];
    const float* b2   = (const float*)d_in[7];
    const float* w3   = (const float*)d_in[8];
    const float* b3   = (const float*)d_in[9];
    const float* wm   = (const float*)d_in[10];
    const float* bm   = (const float*)d_in[11];

    float* out     = (float*)d_out;
    float* maskOut = out;           // (1,1,256,256)
    float* featOut = out + P2;      // (1,256,256,256)

    const int T = 256;

    cudaFuncSetAttribute(k_conv2mma,
                         cudaFuncAttributeMaxDynamicSharedMemorySize, SMEM_C2);
    cudaFuncSetAttribute(k_mma1x1<5, 0>,
                         cudaFuncAttributeMaxDynamicSharedMemorySize, SMEM_1X1);
    cudaFuncSetAttribute(k_mma1x1<4, 1>,
                         cudaFuncAttributeMaxDynamicSharedMemorySize, SMEM_1X1);

    // weight preps (no deps)
    k_prepw <<<(WT_ELEMS + T - 1) / T, T>>>(w2);
    k_prepw1<<<(2 * 256 * K1PAD + T - 1) / T, T>>>(w1);
    k_prepw3<<<(2 * 256 * 256 + T - 1) / T, T>>>(w3);
    // 1. upsample -> g_A
    k_upsample<<<(C_IN * P2 + T - 1) / T, T>>>(fg, bg, mask, feat);
    // 2. guide + box statistics
    k_guide <<<(P2 + T - 1) / T, T>>>();
    k_istats<<<(P2 + T - 1) / T, T>>>();
    // 3. conv1 input prep (transpose -> px-major hi/lo)
    k_prepact1<<<dim3(P2 / 32, K1PAD / 32), dim3(32, 8)>>>();
    // 4. conv1 mma -> g_H
    k_mma1x1<5, 0><<<dim3(512, 2), 256, SMEM_1X1>>>(b1, nullptr);
    // 5. conv2 mma -> g_Ct
    k_conv2mma<<<dim3(512, 2), 256, SMEM_C2>>>(b2);
    // 6. guided filter (fused, 2 passes); pass B writes conv3 input g_V
    k_gfA<<<dim3(32, 8, 8), 256>>>();
    k_gfB<<<dim3(32, 8, 8), 256>>>();
    // 7. conv3 mma -> featOut
    k_mma1x1<4, 1><<<dim3(512, 2), 256, SMEM_1X1>>>(b3, featOut);
    // 8. mask head
    k_maskhead<<<(P2 + T - 1) / T, T>>>(featOut, wm, bm, maskOut);
}

// round 9
// speedup vs baseline: 1.0371x; 1.0371x over previous
#include <cuda_runtime.h>
#include <cuda_bf16.h>
#include <math.h>
#include <stdint.h>

// ---------------------------------------------------------------------------
// GuidedUpsampleUnitGF — conv1/conv2/conv3 via mma.sync bf16 (3-term split)
// NOTE: __device__ globals must NEVER be passed as kernel args from host
//       (host sees shadow symbol -> ATS-readable zeros). Select in device code.
// ---------------------------------------------------------------------------

#define P2    65536
#define C_IN  263
#define CE    256
#define EPS_GF 0.01f

// padded activation planes for conv2: [split 2][py 260][px 264][ch 256] bf16
#define PADH 260
#define PADW 264
#define PADP (PADH * PADW)
#define HPLANE ((size_t)PADP * 256)

#define WT_ELEMS (2 * 25 * 256 * 256)

#define K1PAD 320
#define UPLANE ((size_t)P2 * K1PAD)
#define VPLANE ((size_t)P2 * 256)

#define STAGE_BYTES 65536
#define SMEM_1X1 (3 * STAGE_BYTES)

// conv2 smem: A ring 3 x 32KB, B ring 2 x 33792 (132 rows x 128B x hi/lo)
#define C2_A_STAGE 32768
#define C2_B_OFF   98304
#define C2_B_SLOT  33792
#define C2_B_SPLIT 16896
#define SMEM_C2    (C2_B_OFF + 2 * C2_B_SLOT)   // 165888

// -------------------- scratch ----------------------------------------------
__device__ __align__(256) float g_Ct[(size_t)P2 * 256]; // px-major conv2 out
__device__ __align__(256) float g_Aa[(size_t)P2 * 256]; // 'a' of guided filter
__device__ __align__(256) float g_D [(size_t)P2 * 256];
__device__ __align__(256) float g_E [(size_t)P2 * 256];
__device__ __align__(256) float g_F [(size_t)P2 * 256]; // 'b' of guided filter
__device__ __align__(256) float g_guide[P2];
__device__ __align__(256) float g_meanI[P2];
__device__ __align__(256) float g_varI[P2];
__device__ __align__(256) __nv_bfloat16 g_H [2 * HPLANE];     // conv1 out hi/lo padded
__device__ __align__(256) __nv_bfloat16 g_Wt[WT_ELEMS];       // conv2 W hi/lo
__device__ __align__(256) __nv_bfloat16 g_U [2 * UPLANE];     // conv1 input px-major hi/lo
__device__ __align__(256) __nv_bfloat16 g_V [2 * VPLANE];     // conv3 input hi/lo (filt)
__device__ __align__(256) __nv_bfloat16 g_W1[2 * 256 * K1PAD];
__device__ __align__(256) __nv_bfloat16 g_W3[2 * 256 * 256];

// -------------------- helpers ----------------------------------------------
__device__ __forceinline__ uint32_t smem_u32(const void* p) {
    uint32_t a;
    asm("{ .reg .u64 t; cvta.to.shared.u64 t, %1; cvt.u32.u64 %0, t; }" : "=r"(a) : "l"(p));
    return a;
}
__device__ __forceinline__ void cpa16(uint32_t dst, const void* src) {
    asm volatile("cp.async.cg.shared.global [%0], [%1], 16;\n" :: "r"(dst), "l"(src));
}
__device__ __forceinline__ void ldsm4(uint32_t* r, uint32_t addr) {
    asm volatile("ldmatrix.sync.aligned.m8n8.x4.shared.b16 {%0,%1,%2,%3}, [%4];"
                 : "=r"(r[0]), "=r"(r[1]), "=r"(r[2]), "=r"(r[3]) : "r"(addr));
}
__device__ __forceinline__ void mma_bf16(float* d, const uint32_t* a,
                                         uint32_t b0, uint32_t b1) {
    asm volatile("mma.sync.aligned.m16n8k16.row.col.f32.bf16.bf16.f32 "
                 "{%0,%1,%2,%3}, {%4,%5,%6,%7}, {%8,%9}, {%0,%1,%2,%3};"
                 : "+f"(d[0]), "+f"(d[1]), "+f"(d[2]), "+f"(d[3])
                 : "r"(a[0]), "r"(a[1]), "r"(a[2]), "r"(a[3]), "r"(b0), "r"(b1));
}

// -------------------- fused upsample + transpose + split -> g_U -------------
// grid (P2/32, K1PAD/32), block (32, 8)
__global__ void __launch_bounds__(256) k_upT(const float* __restrict__ fg,
                                             const float* __restrict__ bg,
                                             const float* __restrict__ mask,
                                             const float* __restrict__ feat)
{
    __shared__ float tile[32][33];
    const int p0 = blockIdx.x * 32;
    const int c0 = blockIdx.y * 32;
    const int tx = threadIdx.x, ty = threadIdx.y;

    // bilinear geometry for pixel p0+tx (shared by all channels)
    int p = p0 + tx;
    int y = p >> 8, x = p & 255;
    float sy = 0.5f * (float)y - 0.25f;
    float sx = 0.5f * (float)x - 0.25f;
    float fy = sy - floorf(sy);
    float fx = sx - floorf(sx);
    int y0 = (int)floorf(sy);
    int x0 = (int)floorf(sx);
    int y0c = max(y0, 0),       x0c = max(x0, 0);
    int y1c = min(y0 + 1, 127), x1c = min(x0 + 1, 127);
    int i00 = y0c * 128 + x0c, i01 = y0c * 128 + x1c;
    int i10 = y1c * 128 + x0c, i11 = y1c * 128 + x1c;
    float w00 = (1.f - fy) * (1.f - fx), w01 = (1.f - fy) * fx;
    float w10 = fy * (1.f - fx),         w11 = fy * fx;

#pragma unroll
    for (int k = 0; k < 4; k++) {
        int ch = c0 + ty + k * 8;
        float v = 0.f;
        if (ch < C_IN) {
            const float* src;
            if (ch == 0)      src = mask;
            else if (ch <= 3) src = fg + (ch - 1) * 16384;
            else if (ch <= 6) src = bg + (ch - 4) * 16384;
            else              src = feat + (ch - 7) * 16384;
            v = w00 * src[i00] + w01 * src[i01] + w10 * src[i10] + w11 * src[i11];
        }
        tile[ty + k * 8][tx] = v;
    }
    __syncthreads();
#pragma unroll
    for (int k = 0; k < 4; k++) {
        int pp = p0 + ty + k * 8;
        int ch = c0 + tx;
        float v = tile[tx][ty + k * 8];
        __nv_bfloat16 hi = __float2bfloat16(v);
        g_U[(size_t)pp * K1PAD + ch] = hi;
        g_U[UPLANE + (size_t)pp * K1PAD + ch] = __float2bfloat16(v - __bfloat162float(hi));
    }
}

// guide from g_U (hi+lo reconstruct, channels 1..3 = fg)
__global__ void k_guide()
{
    int p = blockIdx.x * blockDim.x + threadIdx.x;
    if (p >= P2) return;
    float s = 0.f;
#pragma unroll
    for (int c = 1; c <= 3; c++) {
        s += __bfloat162float(g_U[(size_t)p * K1PAD + c])
           + __bfloat162float(g_U[UPLANE + (size_t)p * K1PAD + c]);
    }
    g_guide[p] = s * (128.0f / 3.0f);
}

__device__ __forceinline__ int cnt_axis(int i)
{
    return min(i + 2, 255) - max(i - 2, 0) + 1;
}

__global__ void k_istats()
{
    int p = blockIdx.x * blockDim.x + threadIdx.x;
    if (p >= P2) return;
    int y = p >> 8, x = p & 255;
    float sI = 0.f, sI2 = 0.f;
    for (int dy = -2; dy <= 2; dy++) {
        int yy = y + dy;
        if (yy < 0 || yy > 255) continue;
        for (int dx = -2; dx <= 2; dx++) {
            int xx = x + dx;
            if (xx < 0 || xx > 255) continue;
            float v = g_guide[yy * 256 + xx];
            sI += v; sI2 += v * v;
        }
    }
    float inv = 1.f / (float)(cnt_axis(y) * cnt_axis(x));
    float mI = sI * inv;
    g_meanI[p] = mI;
    g_varI[p]  = sI2 * inv - mI * mI;
}

// -------------------- weight prep kernels ----------------------------------
// conv2 weights: g_Wt[s][tap][m][ch]
__global__ void k_prepw(const float* __restrict__ w2)
{
    int idx = blockIdx.x * blockDim.x + threadIdx.x;
    if (idx >= WT_ELEMS) return;
    int ch = idx & 255;
    int m  = (idx >> 8) & 255;
    int st = idx >> 16;
    int tap = st % 25;
    int s   = st / 25;
    float w = w2[(size_t)m * 6400 + ch * 25 + tap];
    __nv_bfloat16 hi = __float2bfloat16(w);
    g_Wt[idx] = s ? __float2bfloat16(w - __bfloat162float(hi)) : hi;
}

// conv1 weights: g_W1[s][m][320] (zero-pad ch >= 263)
__global__ void k_prepw1(const float* __restrict__ w1)
{
    int idx = blockIdx.x * blockDim.x + threadIdx.x;
    if (idx >= 2 * 256 * K1PAD) return;
    int ch = idx % K1PAD;
    int m  = (idx / K1PAD) & 255;
    int s  = idx / (K1PAD * 256);
    float w = (ch < C_IN) ? w1[(size_t)m * C_IN + ch] : 0.f;
    __nv_bfloat16 hi = __float2bfloat16(w);
    g_W1[idx] = s ? __float2bfloat16(w - __bfloat162float(hi)) : hi;
}

// conv3 weights: g_W3[s][m][256]
__global__ void k_prepw3(const float* __restrict__ w3)
{
    int idx = blockIdx.x * blockDim.x + threadIdx.x;
    if (idx >= 2 * 256 * 256) return;
    int ch = idx & 255;
    int m  = (idx >> 8) & 255;
    int s  = idx >> 16;
    float w = w3[(size_t)m * 256 + ch];
    __nv_bfloat16 hi = __float2bfloat16(w);
    g_W3[idx] = s ? __float2bfloat16(w - __bfloat162float(hi)) : hi;
}

// -------------------- generic 1x1 conv MMA kernel --------------------------
// MODE 0: A=g_W1, B=g_U, epilogue -> g_H bf16 hi/lo padded px-major (conv1)
// MODE 1: A=g_W3, B=g_V, epilogue -> Out fp32 ch-major (conv3)
template<int NKC, int MODE>
__global__ void __launch_bounds__(256, 1) k_mma1x1(const float* __restrict__ bias,
                                                   float* __restrict__ Out)
{
    constexpr int KPAD = NKC * 64;
    constexpr long APLANE_B = (long)256 * KPAD * 2;
    constexpr long BPLANE_B = (long)P2 * KPAD * 2;

    extern __shared__ __align__(1024) char smem[];
    uint32_t sb = smem_u32(smem);
    const int tid = threadIdx.x;
    const int lane = tid & 31, wid = tid >> 5;
    const int wm = wid >> 1, wn = wid & 1;
    const int n0 = blockIdx.x * 128;
    const int m0 = blockIdx.y * 128;

    const int rb = tid >> 3;
    const int cc = tid & 7;
    // device-side symbol references (NOT kernel args!)
    const char* AB = (MODE == 0) ? (const char*)g_W1 : (const char*)g_W3;
    const char* BB = (MODE == 0) ? (const char*)g_U  : (const char*)g_V;

    uint32_t aRow[2], aSw[2];
    const uint32_t aHi = lane >> 4;
#pragma unroll
    for (int f = 0; f < 2; f++) {
        int r = wm * 32 + f * 16 + (lane & 15);
        aRow[f] = r << 7;
        aSw[f] = r & 7;
    }
    uint32_t bRow[4], bSw[4];
    const uint32_t bHi = (lane >> 3) & 1;
#pragma unroll
    for (int g = 0; g < 4; g++) {
        int r = wn * 64 + g * 16 + (lane & 7) + ((lane >> 4) << 3);
        bRow[g] = r << 7;
        bSw[g] = r & 7;
    }

    float acc[2][8][4];
#pragma unroll
    for (int i = 0; i < 2; i++)
#pragma unroll
        for (int j = 0; j < 8; j++)
#pragma unroll
            for (int e = 0; e < 4; e++) acc[i][j][e] = 0.f;

    auto fill = [&](int it) {
        uint32_t stg = sb + (it % 3) * STAGE_BYTES;
        long kO = (long)it * 128;   // 64 ch * 2B
#pragma unroll
        for (int t = 0; t < 4; t++) {
            int r = rb + 32 * t;
            uint32_t sw = (uint32_t)((cc ^ (r & 7)) << 4);
            long a0 = (long)(m0 + r) * (KPAD * 2) + kO + cc * 16;
            cpa16(stg + r * 128 + sw,         AB + a0);
            cpa16(stg + 16384 + r * 128 + sw, AB + a0 + APLANE_B);
            long b0 = (long)(n0 + r) * (KPAD * 2) + kO + cc * 16;
            cpa16(stg + 32768 + r * 128 + sw, BB + b0);
            cpa16(stg + 49152 + r * 128 + sw, BB + b0 + BPLANE_B);
        }
        asm volatile("cp.async.commit_group;" ::: "memory");
    };

    fill(0);
    fill(1);

    for (int it = 0; it < NKC; it++) {
        if (it == NKC - 1) asm volatile("cp.async.wait_group 0;" ::: "memory");
        else               asm volatile("cp.async.wait_group 1;" ::: "memory");
        __syncthreads();
        uint32_t stg = sb + (it % 3) * STAGE_BYTES;
#pragma unroll
        for (int ks = 0; ks < 4; ks++) {
            uint32_t Wh[2][4], Wl[2][4], Bh[4][4], Bl[4][4];
#pragma unroll
            for (int f = 0; f < 2; f++) {
                uint32_t col = ((((uint32_t)(ks << 1) + aHi) ^ aSw[f]) << 4);
                ldsm4(Wh[f], stg + aRow[f] + col);
                ldsm4(Wl[f], stg + 16384 + aRow[f] + col);
            }
#pragma unroll
            for (int g = 0; g < 4; g++) {
                uint32_t col = ((((uint32_t)(ks << 1) + bHi) ^ bSw[g]) << 4);
                ldsm4(Bh[g], stg + 32768 + bRow[g] + col);
                ldsm4(Bl[g], stg + 49152 + bRow[g] + col);
            }
#pragma unroll
            for (int f = 0; f < 2; f++)
#pragma unroll
                for (int g = 0; g < 4; g++)
#pragma unroll
                    for (int h = 0; h < 2; h++) {
                        float* d = acc[f][g * 2 + h];
                        mma_bf16(d, Wh[f], Bh[g][h * 2], Bh[g][h * 2 + 1]);
                        mma_bf16(d, Wh[f], Bl[g][h * 2], Bl[g][h * 2 + 1]);
                        mma_bf16(d, Wl[f], Bh[g][h * 2], Bh[g][h * 2 + 1]);
                    }
        }
        if (it + 2 < NKC) fill(it + 2);
    }
    __syncthreads();

    // ---- staged epilogue ----
    const int l4 = lane >> 2, l2 = (lane & 3) * 2;
    if (MODE == 0) {
        uint32_t* sU = (uint32_t*)smem;   // [n 128][pitch 130] packed (hi,lo)
#pragma unroll
        for (int f = 0; f < 2; f++) {
            int mb = wm * 32 + f * 16 + l4;
            float b0v = bias[m0 + mb], b1v = bias[m0 + mb + 8];
#pragma unroll
            for (int j = 0; j < 8; j++) {
                int nl = wn * 64 + j * 8 + l2;
#pragma unroll
                for (int e = 0; e < 4; e++) {
                    float v = acc[f][j][e] + ((e & 2) ? b1v : b0v);
                    v = fmaxf(v, 0.f);
                    __nv_bfloat16 hi = __float2bfloat16(v);
                    __nv_bfloat16 lo = __float2bfloat16(v - __bfloat162float(hi));
                    uint32_t u = (uint32_t)__bfloat16_as_ushort(hi)
                               | ((uint32_t)__bfloat16_as_ushort(lo) << 16);
                    sU[(nl + (e & 1)) * 130 + mb + ((e & 2) ? 8 : 0)] = u;
                }
            }
        }
        __syncthreads();
#pragma unroll 8
        for (int t = 0; t < 64; t++) {
            int idx = tid + t * 256;
            int row = idx >> 7, ml = idx & 127;
            uint32_t u = sU[row * 130 + ml];
            int ng = n0 + row;
            size_t pixpad = (size_t)(((ng >> 8) + 2) * PADW + (ng & 255) + 2) * 256 + m0 + ml;
            g_H[pixpad] = __ushort_as_bfloat16((unsigned short)(u & 0xFFFF));
            g_H[HPLANE + pixpad] = __ushort_as_bfloat16((unsigned short)(u >> 16));
        }
    } else {
        float* sF = (float*)smem;   // [m 128][pitch 130]
#pragma unroll
        for (int f = 0; f < 2; f++) {
            int mb = wm * 32 + f * 16 + l4;
            float b0v = bias[m0 + mb], b1v = bias[m0 + mb + 8];
#pragma unroll
            for (int j = 0; j < 8; j++) {
                int nl = wn * 64 + j * 8 + l2;
#pragma unroll
                for (int e = 0; e < 4; e++) {
                    float v = acc[f][j][e] + ((e & 2) ? b1v : b0v);
                    sF[(mb + ((e & 2) ? 8 : 0)) * 130 + nl + (e & 1)] = fmaxf(v, 0.f);
                }
            }
        }
        __syncthreads();
#pragma unroll 8
        for (int t = 0; t < 64; t++) {
            int idx = tid + t * 256;
            int ml = idx >> 7, nl = idx & 127;
            Out[(size_t)(m0 + ml) * P2 + n0 + nl] = sF[ml * 130 + nl];
        }
    }
}

// -------------------- conv2: mma.sync bf16, B reused across dx -------------
// loop order: it = (dy*4 + chunk)*5 + dx ; B tile (132 halo rows) per (dy,chunk)
__global__ void __launch_bounds__(256, 1) k_conv2mma(const float* __restrict__ bias2)
{
    extern __shared__ __align__(1024) char smem[];
    uint32_t sb = smem_u32(smem);
    const int tid = threadIdx.x;
    const int lane = tid & 31, wid = tid >> 5;
    const int wm = wid >> 1, wn = wid & 1;
    const int bx = blockIdx.x;
    const int y = bx >> 1, x0 = (bx & 1) * 128;
    const int m0 = blockIdx.y * 128;
    const int pixbase = y * 256 + x0;

    const int rb = tid >> 3;
    const int cc = tid & 7;
    const char* WtB = (const char*)g_Wt;
    const char* HB  = (const char*)g_H;

    uint32_t aRow[2], aSw[2];
    const uint32_t aHi = lane >> 4;
#pragma unroll
    for (int f = 0; f < 2; f++) {
        int r = wm * 32 + f * 16 + (lane & 15);
        aRow[f] = r << 7;
        aSw[f] = r & 7;
    }
    uint32_t rB0[4];
    const uint32_t bHi = (lane >> 3) & 1;
#pragma unroll
    for (int g = 0; g < 4; g++)
        rB0[g] = wn * 64 + g * 16 + (lane & 7) + ((lane >> 4) << 3);

    float acc[2][8][4];
#pragma unroll
    for (int i = 0; i < 2; i++)
#pragma unroll
        for (int j = 0; j < 8; j++)
#pragma unroll
            for (int e = 0; e < 4; e++) acc[i][j][e] = 0.f;

    auto fill = [&](int it) {
        int dy = it / 20, rem = it % 20, chunk = rem / 5, dx = rem % 5;
        int tap = dy * 5 + dx;
        const char* srcA = WtB + (long)tap * 131072 + chunk * 128;
        uint32_t stgA = sb + (it % 3) * C2_A_STAGE;
#pragma unroll
        for (int t = 0; t < 4; t++) {
            int r = rb + 32 * t;
            uint32_t sw = (uint32_t)((cc ^ (r & 7)) << 4);
            long a0 = (long)(m0 + r) * 512 + cc * 16;
            cpa16(stgA + r * 128 + sw,         srcA + a0);
            cpa16(stgA + 16384 + r * 128 + sw, srcA + a0 + 3276800);
        }
        if (dx == 0) {
            uint32_t stgB = sb + C2_B_OFF + ((it / 5) & 1) * C2_B_SLOT;
            const char* srcB = HB + (long)((y + dy) * PADW + x0) * 512 + chunk * 128;
            for (int o = tid * 16; o < C2_B_SPLIT; o += 4096) {
                int r = o >> 7;
                int cB = o & 127;
                uint32_t sw = (uint32_t)(r * 128 + (cB ^ ((r & 7) << 4)));
                cpa16(stgB + sw,              srcB + (long)r * 512 + cB);
                cpa16(stgB + C2_B_SPLIT + sw, srcB + (long)r * 512 + cB + (long)HPLANE * 2);
            }
        }
        asm volatile("cp.async.commit_group;" ::: "memory");
    };

    fill(0);
    fill(1);

    for (int it = 0; it < 100; it++) {
        if (it == 99) asm volatile("cp.async.wait_group 0;" ::: "memory");
        else          asm volatile("cp.async.wait_group 1;" ::: "memory");
        __syncthreads();
        const int dxi = it % 5;
        uint32_t stgA = sb + (it % 3) * C2_A_STAGE;
        uint32_t stgB = sb + C2_B_OFF + ((it / 5) & 1) * C2_B_SLOT;
#pragma unroll
        for (int ks = 0; ks < 4; ks++) {
            uint32_t Wh[2][4], Wl[2][4], Bh[4][4], Bl[4][4];
#pragma unroll
            for (int f = 0; f < 2; f++) {
                uint32_t col = ((((uint32_t)(ks << 1) + aHi) ^ aSw[f]) << 4);
                ldsm4(Wh[f], stgA + aRow[f] + col);
                ldsm4(Wl[f], stgA + 16384 + aRow[f] + col);
            }
#pragma unroll
            for (int g = 0; g < 4; g++) {
                uint32_t rr = rB0[g] + dxi;
                uint32_t addr = stgB + (rr << 7)
                              + ((((uint32_t)(ks << 1) + bHi) ^ (rr & 7)) << 4);
                ldsm4(Bh[g], addr);
                ldsm4(Bl[g], addr + C2_B_SPLIT);
            }
#pragma unroll
            for (int f = 0; f < 2; f++)
#pragma unroll
                for (int g = 0; g < 4; g++)
#pragma unroll
                    for (int h = 0; h < 2; h++) {
                        float* d = acc[f][g * 2 + h];
                        mma_bf16(d, Wh[f], Bh[g][h * 2], Bh[g][h * 2 + 1]);
                        mma_bf16(d, Wh[f], Bl[g][h * 2], Bl[g][h * 2 + 1]);
                        mma_bf16(d, Wl[f], Bh[g][h * 2], Bh[g][h * 2 + 1]);
                    }
        }
        if (it + 2 < 100) fill(it + 2);
    }
    __syncthreads();

    // staged epilogue -> g_Ct px-major, coalesced
    const int l4 = lane >> 2, l2 = (lane & 3) * 2;
    float* sF = (float*)smem;   // [n 128][pitch 130]
#pragma unroll
    for (int f = 0; f < 2; f++) {
        int mb = wm * 32 + f * 16 + l4;
        float b0v = bias2[m0 + mb], b1v = bias2[m0 + mb + 8];
#pragma unroll
        for (int j = 0; j < 8; j++) {
            int nl = wn * 64 + j * 8 + l2;
#pragma unroll
            for (int e = 0; e < 4; e++) {
                float v = acc[f][j][e] + ((e & 2) ? b1v : b0v);
                sF[(nl + (e & 1)) * 130 + mb + ((e & 2) ? 8 : 0)] = fmaxf(v, 0.f);
            }
        }
    }
    __syncthreads();
#pragma unroll 8
    for (int t = 0; t < 64; t++) {
        int idx = tid + t * 256;
        int row = idx >> 7, ml = idx & 127;
        g_Ct[(size_t)(pixbase + row) * 256 + m0 + ml] = sF[row * 130 + ml];
    }
}

// -------------------- guided filter (px-major, wide kernels) ---------------
__global__ void k_gf_row1()
{
    int idx = blockIdx.x * blockDim.x + threadIdx.x;
    if (idx >= CE * P2) return;
    int c = idx & 255;
    int pp = idx >> 8;
    int y = pp >> 8, x = pp & 255;
    size_t rowbase = (size_t)(y * 256) * 256 + c;
    float sp = 0.f, sip = 0.f;
    for (int dxx = -2; dxx <= 2; dxx++) {
        int xx = x + dxx;
        if (xx < 0 || xx > 255) continue;
        float pv = g_Ct[rowbase + (size_t)xx * 256];
        sp  += pv;
        sip += pv * g_guide[y * 256 + xx];
    }
    g_D[idx] = sp;
    g_E[idx] = sip;
}

__global__ void k_gf_col1()
{
    int idx = blockIdx.x * blockDim.x + threadIdx.x;
    if (idx >= CE * P2) return;
    int pp = idx >> 8;
    int y = pp >> 8, x = pp & 255;
    float sp = 0.f, sip = 0.f;
    for (int dyy = -2; dyy <= 2; dyy++) {
        int yy = y + dyy;
        if (yy < 0 || yy > 255) continue;
        int off = idx + (dyy << 16);
        sp  += g_D[off];
        sip += g_E[off];
    }
    float inv = 1.f / (float)(cnt_axis(y) * cnt_axis(x));
    float mp  = sp * inv;
    float mIp = sip * inv;
    float mI  = g_meanI[pp];
    float a = (mIp - mI * mp) / (g_varI[pp] + EPS_GF);
    g_Aa[idx] = a;
    g_F[idx] = mp - a * mI;
}

__global__ void k_gf_row2()
{
    int idx = blockIdx.x * blockDim.x + threadIdx.x;
    if (idx >= CE * P2) return;
    int c = idx & 255;
    int pp = idx >> 8;
    int y = pp >> 8, x = pp & 255;
    size_t rowbase = (size_t)(y * 256) * 256 + c;
    float sa = 0.f, sb = 0.f;
    for (int dxx = -2; dxx <= 2; dxx++) {
        int xx = x + dxx;
        if (xx < 0 || xx > 255) continue;
        sa += g_Aa[rowbase + (size_t)xx * 256];
        sb += g_F [rowbase + (size_t)xx * 256];
    }
    g_D[idx] = sa;
    g_E[idx] = sb;
}

// col2 emits filt directly as bf16 hi/lo into g_V (conv3 input)
__global__ void k_gf_col2()
{
    int idx = blockIdx.x * blockDim.x + threadIdx.x;
    if (idx >= CE * P2) return;
    int pp = idx >> 8;
    int y = pp >> 8, x = pp & 255;
    float sa = 0.f, sb = 0.f;
    for (int dyy = -2; dyy <= 2; dyy++) {
        int yy = y + dyy;
        if (yy < 0 || yy > 255) continue;
        int off = idx + (dyy << 16);
        sa += g_D[off];
        sb += g_E[off];
    }
    float inv = 1.f / (float)(cnt_axis(y) * cnt_axis(x));
    float filt = (sa * inv) * g_guide[pp] + sb * inv;
    __nv_bfloat16 fh = __float2bfloat16(filt);
    g_V[idx] = fh;
    g_V[VPLANE + idx] = __float2bfloat16(filt - __bfloat162float(fh));
}

// -------------------- mask head --------------------------------------------
__global__ void k_maskhead(const float* __restrict__ featOut,
                           const float* __restrict__ wm,
                           const float* __restrict__ bm,
                           float* __restrict__ maskOut)
{
    __shared__ float sw[256];
    int tid = threadIdx.x;
    sw[tid] = wm[tid];
    __syncthreads();
    int p = blockIdx.x * blockDim.x + tid;
    if (p >= P2) return;
    float s = bm[0];
#pragma unroll 8
    for (int c = 0; c < 256; c++)
        s += sw[c] * featOut[(size_t)c * P2 + p];
    maskOut[p] = 1.f / (1.f + expf(-s));
}

// ---------------------------------------------------------------------------
extern "C" void kernel_launch(void* const* d_in, const int* in_sizes, int n_in,
                              void* d_out, int out_size)
{
    const float* fg   = (const float*)d_in[0];
    const float* bg   = (const float*)d_in[1];
    const float* mask = (const float*)d_in[2];
    const float* feat = (const float*)d_in[3];
    const float* w1   = (const float*)d_in[4];
    const float* b1   = (const float*)d_in[5];
    const float* w2   = (const float*)d_in[6];
    const float* b2   = (const float*)d_in[7];
    const float* w3   = (const float*)d_in[8];
    const float* b3   = (const float*)d_in[9];
    const float* wm   = (const float*)d_in[10];
    const float* bm   = (const float*)d_in[11];

    float* out     = (float*)d_out;
    float* maskOut = out;           // (1,1,256,256)
    float* featOut = out + P2;      // (1,256,256,256)

    const int T = 256;

    cudaFuncSetAttribute(k_conv2mma,
                         cudaFuncAttributeMaxDynamicSharedMemorySize, SMEM_C2);
    cudaFuncSetAttribute(k_mma1x1<5, 0>,
                         cudaFuncAttributeMaxDynamicSharedMemorySize, SMEM_1X1);
    cudaFuncSetAttribute(k_mma1x1<4, 1>,
                         cudaFuncAttributeMaxDynamicSharedMemorySize, SMEM_1X1);

    // weight preps (no deps)
    k_prepw <<<(WT_ELEMS + T - 1) / T, T>>>(w2);
    k_prepw1<<<(2 * 256 * K1PAD + T - 1) / T, T>>>(w1);
    k_prepw3<<<(2 * 256 * 256 + T - 1) / T, T>>>(w3);
    // 1. fused upsample + transpose + bf16 split -> g_U
    k_upT<<<dim3(P2 / 32, K1PAD / 32), dim3(32, 8)>>>(fg, bg, mask, feat);
    // 2. guide (from g_U) + box statistics
    k_guide <<<(P2 + T - 1) / T, T>>>();
    k_istats<<<(P2 + T - 1) / T, T>>>();
    // 3. conv1 mma -> g_H
    k_mma1x1<5, 0><<<dim3(512, 2), 256, SMEM_1X1>>>(b1, nullptr);
    // 4. conv2 mma -> g_Ct
    k_conv2mma<<<dim3(512, 2), 256, SMEM_C2>>>(b2);
    // 5. guided filter (wide kernels); col2 writes conv3 input g_V directly
    int NB = (CE * P2 + T - 1) / T;
    k_gf_row1<<<NB, T>>>();
    k_gf_col1<<<NB, T>>>();
    k_gf_row2<<<NB, T>>>();
    k_gf_col2<<<NB, T>>>();
    // 6. conv3 mma -> featOut
    k_mma1x1<4, 1><<<dim3(512, 2), 256, SMEM_1X1>>>(b3, featOut);
    // 7. mask head
    k_maskhead<<<(P2 + T - 1) / T, T>>>(featOut, wm, bm, maskOut);
}